// round 3
// baseline (speedup 1.0000x reference)
#include <cuda_runtime.h>

#define B_   32
#define D_   512
#define T_   64
#define R_   49
#define N_   3136          // T_*R_
#define K_   64
#define OUT_ 1024
#define KD_  32768         // K_*D_

// ---- scratch (static __device__, no allocation) ----
__device__ float g_assign[(size_t)B_ * K_ * N_];   // 25.7 MB
__device__ float g_asum[B_ * K_];
__device__ float g_vlad[(size_t)B_ * K_ * D_];     // 4.2 MB
__device__ float g_bnorm[B_];
__device__ float g_pre[B_ * OUT_];

// ============================================================
// K1: logits = W·x per position, softmax over K, apply mask,
//     store assign[b,k,p].  128 threads, 256 positions/block.
// ============================================================
__global__ __launch_bounds__(128) void k1_assign(
    const float* __restrict__ x, const int* __restrict__ mask,
    const float* __restrict__ conv_w)
{
    __shared__ float sW[K_ * 32];   // [k][dd] chunk of W, 8 KB
    const int b  = blockIdx.y;
    const int p0 = blockIdx.x * 256 + threadIdx.x * 2;
    const bool active = (p0 < N_);

    float a0[K_], a1[K_];
#pragma unroll
    for (int k = 0; k < K_; k++) { a0[k] = 0.f; a1[k] = 0.f; }

    const float* xb = x + (size_t)b * D_ * N_ + p0;

    for (int dc = 0; dc < 16; dc++) {
        const int d0 = dc * 32;
#pragma unroll
        for (int i = 0; i < 16; i++) {
            int idx = threadIdx.x + i * 128;        // idx = k*32+dd
            int k = idx >> 5, dd = idx & 31;
            sW[idx] = conv_w[k * D_ + d0 + dd];
        }
        __syncthreads();
        if (active) {
#pragma unroll 2
            for (int dd = 0; dd < 32; dd++) {
                float2 xv = *(const float2*)(xb + (size_t)(d0 + dd) * N_);
#pragma unroll
                for (int k = 0; k < K_; k++) {
                    float w = sW[k * 32 + dd];
                    a0[k] = fmaf(w, xv.x, a0[k]);
                    a1[k] = fmaf(w, xv.y, a1[k]);
                }
            }
        }
        __syncthreads();
    }
    if (!active) return;

    // softmax over k (stable), then mask
    float m0 = -1e30f, m1 = -1e30f;
#pragma unroll
    for (int k = 0; k < K_; k++) { m0 = fmaxf(m0, a0[k]); m1 = fmaxf(m1, a1[k]); }
    float s0 = 0.f, s1 = 0.f;
#pragma unroll
    for (int k = 0; k < K_; k++) {
        a0[k] = __expf(a0[k] - m0); s0 += a0[k];
        a1[k] = __expf(a1[k] - m1); s1 += a1[k];
    }
    const int t0 = p0 / R_, t1 = (p0 + 1) / R_;
    const float i0 = (float)mask[b * T_ + t0] / s0;
    const float i1 = (float)mask[b * T_ + t1] / s1;

    float* ab = g_assign + (size_t)b * K_ * N_ + p0;
#pragma unroll
    for (int k = 0; k < K_; k++) {
        float2 v; v.x = a0[k] * i0; v.y = a1[k] * i1;
        *(float2*)(ab + (size_t)k * N_) = v;
    }
}

// ============================================================
// K1b: a_sum[b,k] = sum_p assign ; also zeros g_bnorm
// ============================================================
__global__ __launch_bounds__(128) void k1b_asum()
{
    __shared__ float red[128];
    const int row = blockIdx.x;                 // b*K_ + k
    const float* a = g_assign + (size_t)row * N_;
    float s = 0.f;
    for (int i = threadIdx.x; i < N_; i += 128) s += a[i];
    red[threadIdx.x] = s;
    __syncthreads();
    for (int st = 64; st > 0; st >>= 1) {
        if (threadIdx.x < st) red[threadIdx.x] += red[threadIdx.x + st];
        __syncthreads();
    }
    if (threadIdx.x == 0) g_asum[row] = red[0];
    if (blockIdx.x == 0 && threadIdx.x < B_) g_bnorm[threadIdx.x] = 0.f;
}

// ============================================================
// K2: vlad[b,k,d] = sum_p a[k,p]*x[d,p] - a_sum[b,k]*c[k,d]
//     64k x 64d tile per block, 256 threads, 4x4 microtile.
// ============================================================
__global__ __launch_bounds__(256) void k2_vlad(
    const float* __restrict__ x, const float* __restrict__ centroids)
{
    __shared__ float sA[64 * 65];
    __shared__ float sX[64 * 65];
    const int b    = blockIdx.y;
    const int dblk = blockIdx.x * 64;
    const int t    = threadIdx.x;
    const int k0   = (t >> 4) * 4;     // 0..60
    const int dl0  = (t & 15) * 4;     // 0..60

    float acc[4][4];
#pragma unroll
    for (int i = 0; i < 4; i++)
#pragma unroll
        for (int j = 0; j < 4; j++) acc[i][j] = 0.f;

    const float* ab = g_assign + (size_t)b * K_ * N_;
    const float* xb = x + (size_t)b * D_ * N_;

    for (int pc = 0; pc < N_; pc += 64) {
#pragma unroll
        for (int i = 0; i < 16; i++) {
            int idx = t + i * 256;
            int kk = idx >> 6, pp = idx & 63;
            sA[kk * 65 + pp] = ab[(size_t)kk * N_ + pc + pp];
            sX[kk * 65 + pp] = xb[(size_t)(dblk + kk) * N_ + pc + pp];
        }
        __syncthreads();
#pragma unroll 4
        for (int pp = 0; pp < 64; pp++) {
            float av[4], xv[4];
#pragma unroll
            for (int i = 0; i < 4; i++) av[i] = sA[(k0 + i) * 65 + pp];
#pragma unroll
            for (int j = 0; j < 4; j++) xv[j] = sX[(dl0 + j) * 65 + pp];
#pragma unroll
            for (int i = 0; i < 4; i++)
#pragma unroll
                for (int j = 0; j < 4; j++)
                    acc[i][j] = fmaf(av[i], xv[j], acc[i][j]);
        }
        __syncthreads();
    }
#pragma unroll
    for (int i = 0; i < 4; i++) {
        const float as = g_asum[b * K_ + k0 + i];
#pragma unroll
        for (int j = 0; j < 4; j++) {
            const int d = dblk + dl0 + j;
            float c = acc[i][j] - as * centroids[(k0 + i) * D_ + d];
            g_vlad[((size_t)b * K_ + k0 + i) * D_ + d] = c;
        }
    }
}

// ============================================================
// K2b: intra-normalize each (b,k) row over D; accumulate per-b
//      sum of squares of the normalized rows into g_bnorm.
// ============================================================
__global__ __launch_bounds__(128) void k2b_norm()
{
    __shared__ float red[128];
    const int row = blockIdx.x;                 // b*K_ + k
    float* v = g_vlad + (size_t)row * D_;
    const int tid = threadIdx.x;
    float vr[4];
    float ss = 0.f;
#pragma unroll
    for (int i = 0; i < 4; i++) { vr[i] = v[tid + i * 128]; ss += vr[i] * vr[i]; }
    red[tid] = ss;
    __syncthreads();
    for (int st = 64; st > 0; st >>= 1) {
        if (tid < st) red[tid] += red[tid + st];
        __syncthreads();
    }
    const float tot = red[0];
    const float dnm = fmaxf(sqrtf(tot), 1e-12f);
    const float inv = 1.f / dnm;
#pragma unroll
    for (int i = 0; i < 4; i++) v[tid + i * 128] = vr[i] * inv;
    if (tid == 0) atomicAdd(&g_bnorm[row >> 6], tot * inv * inv);
}

// ============================================================
// K3: pre[b,o] = s_b * sum_j v[b,j] * red_w[o,j]
//     8 outputs/block, 32 lanes per output, all 32 b in regs.
// ============================================================
__global__ __launch_bounds__(256) void k3_reduce(const float* __restrict__ red_w)
{
    __shared__ __align__(16) float sv[32 * 260];  // 33.3 KB, padded stride
    const int g = threadIdx.x >> 5, lane = threadIdx.x & 31;
    const int o = blockIdx.x * 8 + g;

    float acc[32];
#pragma unroll
    for (int bb = 0; bb < 32; bb++) acc[bb] = 0.f;

    const float* wrow = red_w + (size_t)o * KD_;

    for (int jc = 0; jc < KD_; jc += 256) {
#pragma unroll
        for (int i = 0; i < 32; i++) {
            int idx = threadIdx.x + i * 256;
            int bb = idx >> 8, jj = idx & 255;
            sv[bb * 260 + jj] = g_vlad[(size_t)bb * KD_ + jc + jj];
        }
        __syncthreads();
#pragma unroll
        for (int half = 0; half < 2; half++) {
            const int jj0 = lane * 4 + half * 128;
            const float4 w4 = *(const float4*)(wrow + jc + jj0);
#pragma unroll
            for (int bb = 0; bb < 32; bb++) {
                const float4 v4 = *(const float4*)&sv[bb * 260 + jj0];
                acc[bb] = fmaf(w4.x, v4.x, acc[bb]);
                acc[bb] = fmaf(w4.y, v4.y, acc[bb]);
                acc[bb] = fmaf(w4.z, v4.z, acc[bb]);
                acc[bb] = fmaf(w4.w, v4.w, acc[bb]);
            }
        }
        __syncthreads();
    }
#pragma unroll
    for (int bb = 0; bb < 32; bb++) {
        float vsum = acc[bb];
#pragma unroll
        for (int off = 16; off; off >>= 1)
            vsum += __shfl_down_sync(0xffffffffu, vsum, off);
        if (lane == 0) {
            const float sb = 1.f / fmaxf(sqrtf(g_bnorm[bb]), 1e-12f);
            g_pre[bb * OUT_ + o] = vsum * sb;
        }
    }
}

// ============================================================
// K4: LayerNorm over OUT_ per b.
// ============================================================
__global__ __launch_bounds__(256) void k4_ln(
    const float* __restrict__ gamma, const float* __restrict__ beta,
    float* __restrict__ out)
{
    __shared__ float red[256];
    const int b = blockIdx.x;
    const int tid = threadIdx.x;
    const float* p = g_pre + b * OUT_;
    float v[4];
    float s = 0.f;
#pragma unroll
    for (int i = 0; i < 4; i++) { v[i] = p[tid + i * 256]; s += v[i]; }
    red[tid] = s;
    __syncthreads();
    for (int st = 128; st > 0; st >>= 1) {
        if (tid < st) red[tid] += red[tid + st];
        __syncthreads();
    }
    const float mu = red[0] * (1.f / OUT_);
    __syncthreads();
    float vs = 0.f;
#pragma unroll
    for (int i = 0; i < 4; i++) { float d = v[i] - mu; vs += d * d; }
    red[tid] = vs;
    __syncthreads();
    for (int st = 128; st > 0; st >>= 1) {
        if (tid < st) red[tid] += red[tid + st];
        __syncthreads();
    }
    const float inv = rsqrtf(red[0] * (1.f / OUT_) + 1e-5f);
#pragma unroll
    for (int i = 0; i < 4; i++) {
        int o = tid + i * 256;
        out[b * OUT_ + o] = (v[i] - mu) * inv * gamma[o] + beta[o];
    }
}

// ============================================================
extern "C" void kernel_launch(void* const* d_in, const int* in_sizes, int n_in,
                              void* d_out, int out_size)
{
    const float* x         = (const float*)d_in[0];
    const int*   mask      = (const int*)  d_in[1];
    const float* centroids = (const float*)d_in[2];
    const float* conv_w    = (const float*)d_in[3];
    const float* red_w     = (const float*)d_in[4];
    const float* gamma     = (const float*)d_in[5];
    const float* beta      = (const float*)d_in[6];
    float* out = (float*)d_out;

    k1_assign<<<dim3(13, 32), 128>>>(x, mask, conv_w);
    k1b_asum <<<B_ * K_, 128>>>();
    k2_vlad  <<<dim3(8, 32), 256>>>(x, centroids);
    k2b_norm <<<B_ * K_, 128>>>();
    k3_reduce<<<OUT_ / 8, 256>>>(red_w);
    k4_ln    <<<B_, 256>>>(gamma, beta, out);
}

// round 4
// speedup vs baseline: 1.7610x; 1.7610x over previous
#include <cuda_runtime.h>

#define B_   32
#define D_   512
#define T_   64
#define R_   49
#define N_   3136          // T_*R_
#define K_   64
#define OUT_ 1024
#define KD_  32768         // K_*D_
#define JS_  32            // j-splits for k3
#define JPER_ (KD_/JS_)    // 1024

// ---- scratch (static __device__, no allocation) ----
__device__ float g_assign[(size_t)B_ * K_ * N_];   // 25.7 MB
__device__ float g_asum[B_ * K_];
__device__ float g_vlad[(size_t)B_ * K_ * D_];     // 4.2 MB
__device__ float g_bnorm[B_];
__device__ float g_ppart[JS_][B_ * OUT_];          // 4 MB partials

// ============================================================
// K1: logits GEMM (64k x 128p tile) + fused softmax + mask.
// 256 threads, microtile 8k x 4p. av is warp-broadcast.
// ============================================================
__global__ __launch_bounds__(256) void k1_assign(
    const float* __restrict__ x, const int* __restrict__ mask,
    const float* __restrict__ conv_w)
{
    __shared__ __align__(16) float sm[64 * 132];   // 33.8 KB, reused
    float* sW = sm;                 // [16 dd][68]  (transposed W chunk)
    float* sX = sm + 16 * 68;       // [16 dd][132]

    const int b  = blockIdx.y;
    const int P0 = blockIdx.x * 128;
    const int t  = threadIdx.x;
    const int kg = t >> 5;          // 0..7  -> k0 = kg*8 (warp-uniform)
    const int pg = t & 31;          // 0..31 -> p0 = pg*4
    const int k0 = kg * 8;
    const int p0 = pg * 4;

    float acc[8][4];
#pragma unroll
    for (int i = 0; i < 8; i++)
#pragma unroll
        for (int j = 0; j < 4; j++) acc[i][j] = 0.f;

    const float* xb = x + (size_t)b * D_ * N_;

    for (int dc = 0; dc < 16; dc++) {
        const int d0 = dc * 32;
        // stage W chunk transposed: sW[dd][k], dd in [0,32) split 2 halves of 16
#pragma unroll
        for (int i = 0; i < 4; i++) {
            int idx = t + i * 256;          // 0..1023 over (k,dd16)
            int kk = idx >> 4, dd = idx & 15;
            sW[dd * 68 + kk] = conv_w[kk * D_ + d0 + dd];      // first 16 dd
        }
        // stage X chunk rows dd=0..15: [16][128]
#pragma unroll
        for (int i = 0; i < 2; i++) {
            int fidx = t + i * 256;         // 0..511 float4s
            int dd = fidx >> 5, pp = (fidx & 31) * 4;
            float4 v = make_float4(0.f, 0.f, 0.f, 0.f);
            if (P0 + pp < N_)
                v = *(const float4*)(xb + (size_t)(d0 + dd) * N_ + P0 + pp);
            *(float4*)&sX[dd * 132 + pp] = v;
        }
        __syncthreads();
#pragma unroll
        for (int dd = 0; dd < 16; dd++) {
            float4 a0 = *(const float4*)&sW[dd * 68 + k0];       // broadcast
            float4 a1 = *(const float4*)&sW[dd * 68 + k0 + 4];   // broadcast
            float4 xv = *(const float4*)&sX[dd * 132 + p0];
            float av[8] = {a0.x,a0.y,a0.z,a0.w,a1.x,a1.y,a1.z,a1.w};
            float pv[4] = {xv.x,xv.y,xv.z,xv.w};
#pragma unroll
            for (int i = 0; i < 8; i++)
#pragma unroll
                for (int j = 0; j < 4; j++)
                    acc[i][j] = fmaf(av[i], pv[j], acc[i][j]);
        }
        __syncthreads();
        // second half dd=16..31 of this 32-chunk
#pragma unroll
        for (int i = 0; i < 4; i++) {
            int idx = t + i * 256;
            int kk = idx >> 4, dd = idx & 15;
            sW[dd * 68 + kk] = conv_w[kk * D_ + d0 + 16 + dd];
        }
#pragma unroll
        for (int i = 0; i < 2; i++) {
            int fidx = t + i * 256;
            int dd = fidx >> 5, pp = (fidx & 31) * 4;
            float4 v = make_float4(0.f, 0.f, 0.f, 0.f);
            if (P0 + pp < N_)
                v = *(const float4*)(xb + (size_t)(d0 + 16 + dd) * N_ + P0 + pp);
            *(float4*)&sX[dd * 132 + pp] = v;
        }
        __syncthreads();
#pragma unroll
        for (int dd = 0; dd < 16; dd++) {
            float4 a0 = *(const float4*)&sW[dd * 68 + k0];
            float4 a1 = *(const float4*)&sW[dd * 68 + k0 + 4];
            float4 xv = *(const float4*)&sX[dd * 132 + p0];
            float av[8] = {a0.x,a0.y,a0.z,a0.w,a1.x,a1.y,a1.z,a1.w};
            float pv[4] = {xv.x,xv.y,xv.z,xv.w};
#pragma unroll
            for (int i = 0; i < 8; i++)
#pragma unroll
                for (int j = 0; j < 4; j++)
                    acc[i][j] = fmaf(av[i], pv[j], acc[i][j]);
        }
        __syncthreads();
    }

    // dump logits to smem [k][132]
#pragma unroll
    for (int i = 0; i < 8; i++)
        *(float4*)&sm[(k0 + i) * 132 + p0] =
            make_float4(acc[i][0], acc[i][1], acc[i][2], acc[i][3]);
    __syncthreads();

    // softmax per column (threads 0..127)
    if (t < 128 && P0 + t < N_) {
        const int p = t;
        float mx = -1e30f;
#pragma unroll 8
        for (int k = 0; k < K_; k++) mx = fmaxf(mx, sm[k * 132 + p]);
        float s = 0.f;
#pragma unroll 8
        for (int k = 0; k < K_; k++) {
            float e = __expf(sm[k * 132 + p] - mx);
            sm[k * 132 + p] = e;
            s += e;
        }
        const int tt = (P0 + p) / R_;
        const float inv = (float)mask[b * T_ + tt] / s;
        float* ab = g_assign + (size_t)b * K_ * N_ + P0 + p;
#pragma unroll 8
        for (int k = 0; k < K_; k++)
            ab[(size_t)k * N_] = sm[k * 132 + p] * inv;
    }
}

// ============================================================
// K1b: a_sum[b,k] = sum_p assign ; also zeros g_bnorm
// ============================================================
__global__ __launch_bounds__(128) void k1b_asum()
{
    __shared__ float red[128];
    const int row = blockIdx.x;                 // b*K_ + k
    const float* a = g_assign + (size_t)row * N_;
    float s = 0.f;
    for (int i = threadIdx.x; i < N_; i += 128) s += a[i];
    red[threadIdx.x] = s;
    __syncthreads();
    for (int st = 64; st > 0; st >>= 1) {
        if (threadIdx.x < st) red[threadIdx.x] += red[threadIdx.x + st];
        __syncthreads();
    }
    if (threadIdx.x == 0) g_asum[row] = red[0];
    if (blockIdx.x == 0 && threadIdx.x < B_) g_bnorm[threadIdx.x] = 0.f;
}

// ============================================================
// K2: vlad[b,k,d] = sum_p a[k,p]*x[d,p] - a_sum*c.
// Tile 64k x 64d, 128 threads, microtile 8k x 4d, p-chunk 32.
// Both smem tiles transposed to [p][·] so loads vectorize.
// ============================================================
__global__ __launch_bounds__(128) void k2_vlad(
    const float* __restrict__ x, const float* __restrict__ centroids)
{
    __shared__ __align__(16) float sA[32 * 68];
    __shared__ __align__(16) float sX[32 * 68];
    const int b    = blockIdx.y;
    const int dblk = blockIdx.x * 64;
    const int t    = threadIdx.x;
    const int kg   = t >> 4;            // 0..7  (warp has 2 kg values)
    const int dg   = t & 15;            // 0..15
    const int k0   = kg * 8;
    const int d0   = dg * 4;

    float acc[8][4];
#pragma unroll
    for (int i = 0; i < 8; i++)
#pragma unroll
        for (int j = 0; j < 4; j++) acc[i][j] = 0.f;

    const float* ab = g_assign + (size_t)b * K_ * N_;
    const float* xb = x + (size_t)b * D_ * N_ + (size_t)dblk * N_;

    for (int pc = 0; pc < N_; pc += 32) {
#pragma unroll
        for (int i = 0; i < 16; i++) {
            int idx = t + i * 128;      // 0..2047 over (row 64, pp 32)
            int rr = idx >> 5, pp = idx & 31;
            sA[pp * 68 + rr] = ab[(size_t)rr * N_ + pc + pp];
            sX[pp * 68 + rr] = xb[(size_t)rr * N_ + pc + pp];
        }
        __syncthreads();
#pragma unroll 4
        for (int pp = 0; pp < 32; pp++) {
            float4 a0 = *(const float4*)&sA[pp * 68 + k0];
            float4 a1 = *(const float4*)&sA[pp * 68 + k0 + 4];
            float4 xv = *(const float4*)&sX[pp * 68 + d0];
            float av[8] = {a0.x,a0.y,a0.z,a0.w,a1.x,a1.y,a1.z,a1.w};
            float dv[4] = {xv.x,xv.y,xv.z,xv.w};
#pragma unroll
            for (int i = 0; i < 8; i++)
#pragma unroll
                for (int j = 0; j < 4; j++)
                    acc[i][j] = fmaf(av[i], dv[j], acc[i][j]);
        }
        __syncthreads();
    }
#pragma unroll
    for (int i = 0; i < 8; i++) {
        const int k = k0 + i;
        const float as = g_asum[b * K_ + k];
        const float4 c4 = *(const float4*)(centroids + k * D_ + dblk + d0);
        float4 o;
        o.x = acc[i][0] - as * c4.x;
        o.y = acc[i][1] - as * c4.y;
        o.z = acc[i][2] - as * c4.z;
        o.w = acc[i][3] - as * c4.w;
        *(float4*)(g_vlad + ((size_t)b * K_ + k) * D_ + dblk + d0) = o;
    }
}

// ============================================================
// K2b: intra-normalize each (b,k) row over D; accumulate per-b
//      sum of squares into g_bnorm.
// ============================================================
__global__ __launch_bounds__(128) void k2b_norm()
{
    __shared__ float red[128];
    const int row = blockIdx.x;                 // b*K_ + k
    float* v = g_vlad + (size_t)row * D_;
    const int tid = threadIdx.x;
    float vr[4];
    float ss = 0.f;
#pragma unroll
    for (int i = 0; i < 4; i++) { vr[i] = v[tid + i * 128]; ss += vr[i] * vr[i]; }
    red[tid] = ss;
    __syncthreads();
    for (int st = 64; st > 0; st >>= 1) {
        if (tid < st) red[tid] += red[tid + st];
        __syncthreads();
    }
    const float tot = red[0];
    const float inv = 1.f / fmaxf(sqrtf(tot), 1e-12f);
#pragma unroll
    for (int i = 0; i < 4; i++) v[tid + i * 128] = vr[i] * inv;
    if (tid == 0) atomicAdd(&g_bnorm[row >> 6], tot * inv * inv);
}

// ============================================================
// K3: partial[b,o] over j-range. Tile 128o x 32b, 128 threads,
// microtile 8o x 4b, j-chunk 64, inner step 2 j.
// ============================================================
__global__ __launch_bounds__(128) void k3_reduce(const float* __restrict__ red_w)
{
    __shared__ __align__(16) float sW[128 * 68];   // [o][j] 34.8 KB
    __shared__ __align__(16) float sV[32 * 68];    // [b][j]  8.7 KB
    const int oblk  = blockIdx.x * 128;
    const int js    = blockIdx.y;
    const int jbase = js * JPER_;
    const int t     = threadIdx.x;
    const int og    = t >> 3;          // 0..15 -> o0 = og*8
    const int bg    = t & 7;           // 0..7  -> b0 = bg*4
    const int o0    = og * 8;
    const int b0    = bg * 4;

    float acc[8][4];
#pragma unroll
    for (int i = 0; i < 8; i++)
#pragma unroll
        for (int j = 0; j < 4; j++) acc[i][j] = 0.f;

    for (int jc = 0; jc < JPER_; jc += 64) {
        const int jg = jbase + jc;
#pragma unroll
        for (int i = 0; i < 16; i++) {
            int idx = t + i * 128;          // 0..2047 float4s over (o 128, j 16f4)
            int oo = idx >> 4, jj = (idx & 15) * 4;
            *(float4*)&sW[oo * 68 + jj] =
                *(const float4*)(red_w + (size_t)(oblk + oo) * KD_ + jg + jj);
        }
#pragma unroll
        for (int i = 0; i < 4; i++) {
            int idx = t + i * 128;          // 0..511 float4s over (b 32, j 16f4)
            int bb = idx >> 4, jj = (idx & 15) * 4;
            *(float4*)&sV[bb * 68 + jj] =
                *(const float4*)(g_vlad + (size_t)bb * KD_ + jg + jj);
        }
        __syncthreads();
#pragma unroll 4
        for (int jj = 0; jj < 64; jj += 2) {
            float2 wv[8], vv[4];
#pragma unroll
            for (int i = 0; i < 8; i++)
                wv[i] = *(const float2*)&sW[(o0 + i) * 68 + jj];
#pragma unroll
            for (int j = 0; j < 4; j++)
                vv[j] = *(const float2*)&sV[(b0 + j) * 68 + jj];
#pragma unroll
            for (int i = 0; i < 8; i++)
#pragma unroll
                for (int j = 0; j < 4; j++) {
                    acc[i][j] = fmaf(wv[i].x, vv[j].x, acc[i][j]);
                    acc[i][j] = fmaf(wv[i].y, vv[j].y, acc[i][j]);
                }
        }
        __syncthreads();
    }
    // unique writer per (js, b, o)
#pragma unroll
    for (int j = 0; j < 4; j++)
#pragma unroll
        for (int i = 0; i < 8; i++)
            g_ppart[js][(b0 + j) * OUT_ + oblk + o0 + i] = acc[i][j];
}

// ============================================================
// K4: sum j-partials, scale by 1/||vlad||, LayerNorm.
// ============================================================
__global__ __launch_bounds__(256) void k4_ln(
    const float* __restrict__ gamma, const float* __restrict__ beta,
    float* __restrict__ out)
{
    __shared__ float red[256];
    const int b = blockIdx.x;
    const int tid = threadIdx.x;
    const float sb = 1.f / fmaxf(sqrtf(g_bnorm[b]), 1e-12f);
    float v[4];
    float s = 0.f;
#pragma unroll
    for (int i = 0; i < 4; i++) {
        const int o = tid + i * 256;
        float acc = 0.f;
#pragma unroll
        for (int js = 0; js < JS_; js++) acc += g_ppart[js][b * OUT_ + o];
        v[i] = acc * sb;
        s += v[i];
    }
    red[tid] = s;
    __syncthreads();
    for (int st = 128; st > 0; st >>= 1) {
        if (tid < st) red[tid] += red[tid + st];
        __syncthreads();
    }
    const float mu = red[0] * (1.f / OUT_);
    __syncthreads();
    float vs = 0.f;
#pragma unroll
    for (int i = 0; i < 4; i++) { float d = v[i] - mu; vs += d * d; }
    red[tid] = vs;
    __syncthreads();
    for (int st = 128; st > 0; st >>= 1) {
        if (tid < st) red[tid] += red[tid + st];
        __syncthreads();
    }
    const float inv = rsqrtf(red[0] * (1.f / OUT_) + 1e-5f);
#pragma unroll
    for (int i = 0; i < 4; i++) {
        int o = tid + i * 256;
        out[b * OUT_ + o] = (v[i] - mu) * inv * gamma[o] + beta[o];
    }
}

// ============================================================
extern "C" void kernel_launch(void* const* d_in, const int* in_sizes, int n_in,
                              void* d_out, int out_size)
{
    const float* x         = (const float*)d_in[0];
    const int*   mask      = (const int*)  d_in[1];
    const float* centroids = (const float*)d_in[2];
    const float* conv_w    = (const float*)d_in[3];
    const float* red_w     = (const float*)d_in[4];
    const float* gamma     = (const float*)d_in[5];
    const float* beta      = (const float*)d_in[6];
    float* out = (float*)d_out;

    k1_assign<<<dim3(25, 32), 256>>>(x, mask, conv_w);
    k1b_asum <<<B_ * K_, 128>>>();
    k2_vlad  <<<dim3(8, 32), 128>>>(x, centroids);
    k2b_norm <<<B_ * K_, 128>>>();
    k3_reduce<<<dim3(OUT_ / 128, JS_), 128>>>(red_w);
    k4_ln    <<<B_, 256>>>(gamma, beta, out);
}

// round 5
// speedup vs baseline: 2.0482x; 1.1631x over previous
#include <cuda_runtime.h>

#define B_   32
#define D_   512
#define T_   64
#define R_   49
#define N_   3136          // T_*R_
#define K_   64
#define OUT_ 1024
#define KD_  32768         // K_*D_
#define JS_  32            // j-splits for k3
#define JPER_ (KD_/JS_)    // 1024

typedef unsigned long long ull;

// packed f32x2 helpers (sm_100+)
#define FMA2(acc, a, b) asm("fma.rn.f32x2 %0, %1, %2, %0;" : "+l"(acc) : "l"(a), "l"(b))
#define DUP2(out, f)    asm("mov.b64 %0, {%1, %1};" : "=l"(out) : "r"(__float_as_uint(f)))
#define UNPK(lo, hi, v) asm("mov.b64 {%0, %1}, %2;" : "=r"(lo), "=r"(hi) : "l"(v))

// ---- scratch (static __device__, no allocation) ----
__device__ float g_assign[(size_t)B_ * K_ * N_];   // 25.7 MB
__device__ float g_asum[B_ * K_];
__device__ float g_vlad[(size_t)B_ * K_ * D_];     // 4.2 MB
__device__ float g_bnorm[B_];
__device__ float g_ppart[JS_][B_ * OUT_];          // 4 MB partials

// ============================================================
// K0: zero the atomically-accumulated buffers.
// ============================================================
__global__ __launch_bounds__(256) void k0_init()
{
    const int t = threadIdx.x;
#pragma unroll
    for (int i = 0; i < 8; i++) g_asum[t + i * 256] = 0.f;
    if (t < B_) g_bnorm[t] = 0.f;
}

// ============================================================
// K1: logits GEMM (64k x 128p tile) + softmax + mask + a_sum.
// 256 threads, microtile 8k x 4p, FFMA2 packed along p.
// ============================================================
__global__ __launch_bounds__(256) void k1_assign(
    const float* __restrict__ x, const int* __restrict__ mask,
    const float* __restrict__ conv_w)
{
    __shared__ __align__(16) float sm[64 * 132];   // 33.8 KB, reused
    float* sW = sm;                 // [16 dd][68]  transposed W chunk
    float* sX = sm + 16 * 68;       // [16 dd][132]

    const int b  = blockIdx.y;
    const int P0 = blockIdx.x * 128;
    const int t  = threadIdx.x;
    const int k0 = (t >> 5) * 8;    // warp-uniform
    const int p0 = (t & 31) * 4;

    ull acc2[8][2];
#pragma unroll
    for (int i = 0; i < 8; i++) { acc2[i][0] = 0ull; acc2[i][1] = 0ull; }

    const float* xb = x + (size_t)b * D_ * N_;

    for (int dc = 0; dc < 32; dc++) {
        const int d0 = dc * 16;
        // stage W chunk transposed: sW[dd][k]
#pragma unroll
        for (int i = 0; i < 4; i++) {
            int idx = t + i * 256;          // (k 64, dd 16)
            int kk = idx >> 4, dd = idx & 15;
            sW[dd * 68 + kk] = conv_w[kk * D_ + d0 + dd];
        }
        // stage X chunk: sX[dd][128p]
#pragma unroll
        for (int i = 0; i < 2; i++) {
            int fidx = t + i * 256;         // 512 float4s
            int dd = fidx >> 5, pp = (fidx & 31) * 4;
            float4 v = make_float4(0.f, 0.f, 0.f, 0.f);
            if (P0 + pp < N_)
                v = *(const float4*)(xb + (size_t)(d0 + dd) * N_ + P0 + pp);
            *(float4*)&sX[dd * 132 + pp] = v;
        }
        __syncthreads();
#pragma unroll 4
        for (int dd = 0; dd < 16; dd++) {
            float4 a0 = *(const float4*)&sW[dd * 68 + k0];       // broadcast
            float4 a1 = *(const float4*)&sW[dd * 68 + k0 + 4];   // broadcast
            ulonglong2 xv = *(const ulonglong2*)&sX[dd * 132 + p0];
            float av[8] = {a0.x,a0.y,a0.z,a0.w,a1.x,a1.y,a1.z,a1.w};
#pragma unroll
            for (int i = 0; i < 8; i++) {
                ull ad; DUP2(ad, av[i]);
                FMA2(acc2[i][0], ad, xv.x);
                FMA2(acc2[i][1], ad, xv.y);
            }
        }
        __syncthreads();
    }

    // dump logits to smem [k][132]
#pragma unroll
    for (int i = 0; i < 8; i++) {
        float4 o;
        UNPK(*(unsigned*)&o.x, *(unsigned*)&o.y, acc2[i][0]);
        UNPK(*(unsigned*)&o.z, *(unsigned*)&o.w, acc2[i][1]);
        *(float4*)&sm[(k0 + i) * 132 + p0] = o;
    }
    __syncthreads();

    // softmax per column + store + a_sum partials (threads 0..127)
    if (t < 128 && P0 + t < N_) {
        const int p = t;
        const int lane = t & 31;
        float mx = -1e30f;
#pragma unroll 8
        for (int k = 0; k < K_; k++) mx = fmaxf(mx, sm[k * 132 + p]);
        float s = 0.f;
#pragma unroll 8
        for (int k = 0; k < K_; k++) {
            float e = __expf(sm[k * 132 + p] - mx);
            sm[k * 132 + p] = e;
            s += e;
        }
        const int tt = (P0 + p) / R_;
        const float inv = (float)mask[b * T_ + tt] / s;
        float* ab = g_assign + (size_t)b * K_ * N_ + P0 + p;
#pragma unroll 4
        for (int k = 0; k < K_; k++) {
            float v = sm[k * 132 + p] * inv;
            ab[(size_t)k * N_] = v;
            // warp-reduce over 32 positions, accumulate a_sum
            float r = v;
#pragma unroll
            for (int off = 16; off; off >>= 1)
                r += __shfl_down_sync(0xffffffffu, r, off);
            if (lane == 0) atomicAdd(&g_asum[b * K_ + k], r);
        }
    }
}

// ============================================================
// K2: vlad[b,k,d] = sum_p a[k,p]*x[d,p] - a_sum*c.
// Tile 64k x 64d, 128 threads, microtile 8k x 4d, FFMA2 along d.
// ============================================================
__global__ __launch_bounds__(128) void k2_vlad(
    const float* __restrict__ x, const float* __restrict__ centroids)
{
    __shared__ __align__(16) float sA[32 * 68];
    __shared__ __align__(16) float sX[32 * 68];
    const int b    = blockIdx.y;
    const int dblk = blockIdx.x * 64;
    const int t    = threadIdx.x;
    const int k0   = (t >> 4) * 8;
    const int d0   = (t & 15) * 4;

    ull acc2[8][2];
#pragma unroll
    for (int i = 0; i < 8; i++) { acc2[i][0] = 0ull; acc2[i][1] = 0ull; }

    const float* ab = g_assign + (size_t)b * K_ * N_;
    const float* xb = x + (size_t)b * D_ * N_ + (size_t)dblk * N_;

    for (int pc = 0; pc < N_; pc += 32) {
#pragma unroll
        for (int i = 0; i < 16; i++) {
            int idx = t + i * 128;      // (row 64, pp 32)
            int rr = idx >> 5, pp = idx & 31;
            sA[pp * 68 + rr] = ab[(size_t)rr * N_ + pc + pp];
            sX[pp * 68 + rr] = xb[(size_t)rr * N_ + pc + pp];
        }
        __syncthreads();
#pragma unroll 4
        for (int pp = 0; pp < 32; pp++) {
            float4 a0 = *(const float4*)&sA[pp * 68 + k0];
            float4 a1 = *(const float4*)&sA[pp * 68 + k0 + 4];
            ulonglong2 xv = *(const ulonglong2*)&sX[pp * 68 + d0];
            float av[8] = {a0.x,a0.y,a0.z,a0.w,a1.x,a1.y,a1.z,a1.w};
#pragma unroll
            for (int i = 0; i < 8; i++) {
                ull ad; DUP2(ad, av[i]);
                FMA2(acc2[i][0], ad, xv.x);
                FMA2(acc2[i][1], ad, xv.y);
            }
        }
        __syncthreads();
    }
#pragma unroll
    for (int i = 0; i < 8; i++) {
        const int k = k0 + i;
        const float as = g_asum[b * K_ + k];
        const float4 c4 = *(const float4*)(centroids + k * D_ + dblk + d0);
        float4 o;
        UNPK(*(unsigned*)&o.x, *(unsigned*)&o.y, acc2[i][0]);
        UNPK(*(unsigned*)&o.z, *(unsigned*)&o.w, acc2[i][1]);
        o.x -= as * c4.x;
        o.y -= as * c4.y;
        o.z -= as * c4.z;
        o.w -= as * c4.w;
        *(float4*)(g_vlad + ((size_t)b * K_ + k) * D_ + dblk + d0) = o;
    }
}

// ============================================================
// K2b: intra-normalize each (b,k) row over D; accumulate per-b
//      sum of squares into g_bnorm.
// ============================================================
__global__ __launch_bounds__(128) void k2b_norm()
{
    __shared__ float red[128];
    const int row = blockIdx.x;                 // b*K_ + k
    float* v = g_vlad + (size_t)row * D_;
    const int tid = threadIdx.x;
    float vr[4];
    float ss = 0.f;
#pragma unroll
    for (int i = 0; i < 4; i++) { vr[i] = v[tid + i * 128]; ss += vr[i] * vr[i]; }
    red[tid] = ss;
    __syncthreads();
    for (int st = 64; st > 0; st >>= 1) {
        if (tid < st) red[tid] += red[tid + st];
        __syncthreads();
    }
    const float tot = red[0];
    const float inv = 1.f / fmaxf(sqrtf(tot), 1e-12f);
#pragma unroll
    for (int i = 0; i < 4; i++) v[tid + i * 128] = vr[i] * inv;
    if (tid == 0) atomicAdd(&g_bnorm[row >> 6], tot * inv * inv);
}

// ============================================================
// K3: partial[b,o] over j-range. Tile 128o x 32b, 128 threads,
// microtile 8o x 4b interleaved ({og+16i},{bg+8j}), FFMA2
// packed along the j reduction dim (zero packing overhead).
// ============================================================
__global__ __launch_bounds__(128) void k3_reduce(const float* __restrict__ red_w)
{
    __shared__ __align__(16) float sW[128 * 68];   // [o][j] 34.8 KB
    __shared__ __align__(16) float sV[32 * 68];    // [b][j]  8.7 KB
    const int oblk  = blockIdx.x * 128;
    const int js    = blockIdx.y;
    const int jbase = js * JPER_;
    const int t     = threadIdx.x;
    const int og    = t >> 3;          // 0..15, o = og + 16i
    const int bg    = t & 7;           // 0..7,  b = bg + 8j

    ull acc2[8][4];
#pragma unroll
    for (int i = 0; i < 8; i++)
#pragma unroll
        for (int j = 0; j < 4; j++) acc2[i][j] = 0ull;

    for (int jc = 0; jc < JPER_; jc += 64) {
        const int jg = jbase + jc;
#pragma unroll
        for (int i = 0; i < 16; i++) {
            int idx = t + i * 128;          // (o 128, j 16 f4)
            int oo = idx >> 4, jj = (idx & 15) * 4;
            *(float4*)&sW[oo * 68 + jj] =
                *(const float4*)(red_w + (size_t)(oblk + oo) * KD_ + jg + jj);
        }
#pragma unroll
        for (int i = 0; i < 4; i++) {
            int idx = t + i * 128;          // (b 32, j 16 f4)
            int bb = idx >> 4, jj = (idx & 15) * 4;
            *(float4*)&sV[bb * 68 + jj] =
                *(const float4*)(g_vlad + (size_t)bb * KD_ + jg + jj);
        }
        __syncthreads();
#pragma unroll 4
        for (int jj = 0; jj < 64; jj += 2) {
            ull wv[8], vv[4];
#pragma unroll
            for (int i = 0; i < 8; i++)
                wv[i] = *(const ull*)&sW[(og + 16 * i) * 68 + jj];
#pragma unroll
            for (int j = 0; j < 4; j++)
                vv[j] = *(const ull*)&sV[(bg + 8 * j) * 68 + jj];
#pragma unroll
            for (int i = 0; i < 8; i++)
#pragma unroll
                for (int j = 0; j < 4; j++)
                    FMA2(acc2[i][j], wv[i], vv[j]);
        }
        __syncthreads();
    }
    // unique writer per (js, b, o); fold the packed pair
#pragma unroll
    for (int j = 0; j < 4; j++)
#pragma unroll
        for (int i = 0; i < 8; i++) {
            float lo, hi;
            UNPK(*(unsigned*)&lo, *(unsigned*)&hi, acc2[i][j]);
            g_ppart[js][(bg + 8 * j) * OUT_ + oblk + og + 16 * i] = lo + hi;
        }
}

// ============================================================
// K4: sum j-partials, scale by 1/||vlad||, LayerNorm.
// ============================================================
__global__ __launch_bounds__(256) void k4_ln(
    const float* __restrict__ gamma, const float* __restrict__ beta,
    float* __restrict__ out)
{
    __shared__ float red[256];
    const int b = blockIdx.x;
    const int tid = threadIdx.x;
    const float sb = 1.f / fmaxf(sqrtf(g_bnorm[b]), 1e-12f);
    float v[4];
    float s = 0.f;
#pragma unroll
    for (int i = 0; i < 4; i++) {
        const int o = tid + i * 256;
        float acc = 0.f;
#pragma unroll
        for (int js = 0; js < JS_; js++) acc += g_ppart[js][b * OUT_ + o];
        v[i] = acc * sb;
        s += v[i];
    }
    red[tid] = s;
    __syncthreads();
    for (int st = 128; st > 0; st >>= 1) {
        if (tid < st) red[tid] += red[tid + st];
        __syncthreads();
    }
    const float mu = red[0] * (1.f / OUT_);
    __syncthreads();
    float vs = 0.f;
#pragma unroll
    for (int i = 0; i < 4; i++) { float d = v[i] - mu; vs += d * d; }
    red[tid] = vs;
    __syncthreads();
    for (int st = 128; st > 0; st >>= 1) {
        if (tid < st) red[tid] += red[tid + st];
        __syncthreads();
    }
    const float inv = rsqrtf(red[0] * (1.f / OUT_) + 1e-5f);
#pragma unroll
    for (int i = 0; i < 4; i++) {
        int o = tid + i * 256;
        out[b * OUT_ + o] = (v[i] - mu) * inv * gamma[o] + beta[o];
    }
}

// ============================================================
extern "C" void kernel_launch(void* const* d_in, const int* in_sizes, int n_in,
                              void* d_out, int out_size)
{
    const float* x         = (const float*)d_in[0];
    const int*   mask      = (const int*)  d_in[1];
    const float* centroids = (const float*)d_in[2];
    const float* conv_w    = (const float*)d_in[3];
    const float* red_w     = (const float*)d_in[4];
    const float* gamma     = (const float*)d_in[5];
    const float* beta      = (const float*)d_in[6];
    float* out = (float*)d_out;

    k0_init  <<<1, 256>>>();
    k1_assign<<<dim3(25, 32), 256>>>(x, mask, conv_w);
    k2_vlad  <<<dim3(8, 32), 128>>>(x, centroids);
    k2b_norm <<<B_ * K_, 128>>>();
    k3_reduce<<<dim3(OUT_ / 128, JS_), 128>>>(red_w);
    k4_ln    <<<B_, 256>>>(gamma, beta, out);
}